// round 17
// baseline (speedup 1.0000x reference)
#include <cuda_runtime.h>
#include <cuda_bf16.h>
#include <cuda_fp16.h>
#include <stdint.h>
#include <math.h>

#define NN 50000
#define NE 800000
#define IND 64
#define ED 16
#define HID 128
#define GG 128
#define EPSV 1e-5f
#define ASTR 132   // padded smem row stride for 128-wide A tiles (bf16 elems)
#define WSTR 66    // padded smem row stride for 64-k W tiles (bf16 elems)
#define EASTR 20   // padded smem row stride for 16-wide edge tiles (bf16 elems)
#define ESTR 132   // E half row stride (halves)

// ---------------- scratch (no allocations allowed) ----------------
__device__ float d_h[(size_t)NN * HID];   // node features
__device__ float d_t[(size_t)NN * HID];   // aggr / mlp buffer
__device__ float d_g[GG * HID];           // pooled per-graph
__device__ int   d_off[GG + 1];           // graph segment offsets

// ---------------- graph offsets (batch is sorted int32) ----------------
__global__ void offsets_kernel(const int* __restrict__ batch) {
    int g = blockIdx.x * blockDim.x + threadIdx.x;
    if (g > GG) return;
    int lo = 0, hi = NN;
    while (lo < hi) {
        int mid = (lo + hi) >> 1;
        if (batch[mid] < g) lo = mid + 1; else hi = mid;
    }
    d_off[g] = lo;
}

// ---------------- bf16 split + mma helpers ----------------
__device__ __forceinline__ void bsplit(float x, __nv_bfloat16& h, __nv_bfloat16& l) {
    h = __float2bfloat16_rn(x);
    l = __float2bfloat16_rn(x - __bfloat162float(h));
}

__device__ __forceinline__ void mma_bf16(float c[4], const uint32_t a[4], const uint32_t b[2]) {
    asm volatile(
        "mma.sync.aligned.m16n8k16.row.col.f32.bf16.bf16.f32 "
        "{%0,%1,%2,%3}, {%4,%5,%6,%7}, {%8,%9}, {%0,%1,%2,%3};"
        : "+f"(c[0]), "+f"(c[1]), "+f"(c[2]), "+f"(c[3])
        : "r"(a[0]), "r"(a[1]), "r"(a[2]), "r"(a[3]), "r"(b[0]), "r"(b[1]));
}

// warp computes 32 x (8*NT) of C += A * W^T, bf16x3 compensated.
template <int NT>
__device__ __forceinline__ void warp_gemm(
    const __nv_bfloat16* __restrict__ Ah, const __nv_bfloat16* __restrict__ Al,
    const __nv_bfloat16* __restrict__ Wh, const __nv_bfloat16* __restrict__ Wl,
    int nch, int astr, int wstr, int akoff,
    int r0, int c0, int grp, int qp, float C[2][NT][4])
{
    for (int ch = 0; ch < nch; ch++) {
        const int kcA = akoff + ch * 16 + qp * 2;
        const int kcW = ch * 16 + qp * 2;
        uint32_t ah[2][4], al[2][4];
        #pragma unroll
        for (int mt = 0; mt < 2; mt++) {
            const __nv_bfloat16* p = Ah + (r0 + mt * 16 + grp) * astr + kcA;
            const __nv_bfloat16* q = Al + (r0 + mt * 16 + grp) * astr + kcA;
            ah[mt][0] = *(const uint32_t*)p;
            ah[mt][1] = *(const uint32_t*)(p + 8 * astr);
            ah[mt][2] = *(const uint32_t*)(p + 8);
            ah[mt][3] = *(const uint32_t*)(p + 8 * astr + 8);
            al[mt][0] = *(const uint32_t*)q;
            al[mt][1] = *(const uint32_t*)(q + 8 * astr);
            al[mt][2] = *(const uint32_t*)(q + 8);
            al[mt][3] = *(const uint32_t*)(q + 8 * astr + 8);
        }
        #pragma unroll
        for (int nt = 0; nt < NT; nt++) {
            const __nv_bfloat16* p = Wh + (c0 + nt * 8 + grp) * wstr + kcW;
            const __nv_bfloat16* q = Wl + (c0 + nt * 8 + grp) * wstr + kcW;
            uint32_t bh[2] = { *(const uint32_t*)p, *(const uint32_t*)(p + 8) };
            uint32_t bl[2] = { *(const uint32_t*)q, *(const uint32_t*)(q + 8) };
            #pragma unroll
            for (int mt = 0; mt < 2; mt++) {
                mma_bf16(C[mt][nt], ah[mt], bh);
                mma_bf16(C[mt][nt], ah[mt], bl);
                mma_bf16(C[mt][nt], al[mt], bh);
            }
        }
    }
}

// load 64 k-rows of W [k][128] transposed into Wt[n][k_local] hi/lo (stride WSTR)
__device__ __forceinline__ void load_wt64(
    const float* __restrict__ w, int krow0,
    __nv_bfloat16* Wh, __nv_bfloat16* Wl, int tid)
{
    for (int i = tid; i < 64 * 32; i += 256) {
        int k = i >> 5, n = (i & 31) * 4;
        float4 v = *(const float4*)(w + (size_t)(krow0 + k) * HID + n);
        __nv_bfloat16 hh, ll;
        bsplit(v.x, hh, ll); Wh[(n + 0) * WSTR + k] = hh; Wl[(n + 0) * WSTR + k] = ll;
        bsplit(v.y, hh, ll); Wh[(n + 1) * WSTR + k] = hh; Wl[(n + 1) * WSTR + k] = ll;
        bsplit(v.z, hh, ll); Wh[(n + 2) * WSTR + k] = hh; Wl[(n + 2) * WSTR + k] = ll;
        bsplit(v.w, hh, ll); Wh[(n + 3) * WSTR + k] = hh; Wl[(n + 3) * WSTR + k] = ll;
    }
}

// ---------------- edge message via tensor cores (512 thr, 16 warps) ----------------
// Tile of 128 edges per CTA: E = ea_tile @ W + b (mma, spilled fp16), then
// aggr[dst] += relu(h[src] + E_row)  via red.v4  (aggr pre-seeded with h).
__global__ __launch_bounds__(512, 2) void msg_mma(
    const int* __restrict__ ei, const float* __restrict__ ea,
    const float* __restrict__ ew, const float* __restrict__ eb,
    const float* __restrict__ h, float* __restrict__ aggr)
{
    extern __shared__ char smraw[];
    __nv_bfloat16* Ah = (__nv_bfloat16*)smraw;         // ea tile hi  [128][EASTR]
    __nv_bfloat16* Al = Ah + 128 * EASTR;              // ea tile lo
    __nv_bfloat16* Wh = Al + 128 * EASTR;              // W^T hi      [128 n][EASTR k]
    __nv_bfloat16* Wl = Wh + 128 * EASTR;              // W^T lo
    __half* E = (__half*)(Wl + 128 * EASTR);           // E fp16      [128][ESTR]

    const int tid = threadIdx.x;
    const int ebase = blockIdx.x * 128;

    for (int i = tid; i < 128 * 4; i += 512) {
        int r = i >> 2, k4 = (i & 3) * 4;
        float4 v = *(const float4*)(ea + (size_t)(ebase + r) * ED + k4);
        __nv_bfloat16 h0, l0, h1, l1, h2, l2, h3, l3;
        bsplit(v.x, h0, l0); bsplit(v.y, h1, l1);
        bsplit(v.z, h2, l2); bsplit(v.w, h3, l3);
        *(__nv_bfloat162*)&Ah[r * EASTR + k4]     = __halves2bfloat162(h0, h1);
        *(__nv_bfloat162*)&Ah[r * EASTR + k4 + 2] = __halves2bfloat162(h2, h3);
        *(__nv_bfloat162*)&Al[r * EASTR + k4]     = __halves2bfloat162(l0, l1);
        *(__nv_bfloat162*)&Al[r * EASTR + k4 + 2] = __halves2bfloat162(l2, l3);
    }
    for (int i = tid; i < 16 * 32; i += 512) {
        int k = i >> 5, n = (i & 31) * 4;
        float4 v = *(const float4*)(ew + (size_t)k * HID + n);
        __nv_bfloat16 hh, ll;
        bsplit(v.x, hh, ll); Wh[(n + 0) * EASTR + k] = hh; Wl[(n + 0) * EASTR + k] = ll;
        bsplit(v.y, hh, ll); Wh[(n + 1) * EASTR + k] = hh; Wl[(n + 1) * EASTR + k] = ll;
        bsplit(v.z, hh, ll); Wh[(n + 2) * EASTR + k] = hh; Wl[(n + 2) * EASTR + k] = ll;
        bsplit(v.w, hh, ll); Wh[(n + 3) * EASTR + k] = hh; Wl[(n + 3) * EASTR + k] = ll;
    }
    __syncthreads();

    const int lane = tid & 31, wid = tid >> 5;          // 16 warps
    const int r0 = (wid & 3) * 32, c0 = (wid >> 2) * 32; // 4x4 grid of 32x32 tiles
    const int grp = lane >> 2, qp = lane & 3;

    float C[2][4][4];
    #pragma unroll
    for (int nt = 0; nt < 4; nt++) {
        float2 bv = *(const float2*)(eb + c0 + nt * 8 + qp * 2);
        #pragma unroll
        for (int mt = 0; mt < 2; mt++) {
            C[mt][nt][0] = bv.x; C[mt][nt][1] = bv.y;
            C[mt][nt][2] = bv.x; C[mt][nt][3] = bv.y;
        }
    }
    warp_gemm<4>(Ah, Al, Wh, Wl, 1, EASTR, EASTR, 0, r0, c0, grp, qp, C);

    #pragma unroll
    for (int mt = 0; mt < 2; mt++) {
        int row = r0 + mt * 16 + grp;
        #pragma unroll
        for (int nt = 0; nt < 4; nt++) {
            int col = c0 + nt * 8 + qp * 2;
            *(__half2*)&E[row * ESTR + col]       = __floats2half2_rn(C[mt][nt][0], C[mt][nt][1]);
            *(__half2*)&E[(row + 8) * ESTR + col] = __floats2half2_rn(C[mt][nt][2], C[mt][nt][3]);
        }
    }

    // warp owns edges [wid*8, wid*8+8); preload 8 src + 8 dst indices
    int rbase = wid * 8;
    int myidx = 0;
    if (lane < 8)       myidx = ei[ebase + rbase + lane];
    else if (lane < 16) myidx = ei[NE + ebase + rbase + (lane - 8)];
    __syncthreads();

    const float4* h4 = (const float4*)h;
    int src = __shfl_sync(0xffffffffu, myidx, 0);
    float4 hv = h4[(size_t)src * 32 + lane];
    #pragma unroll
    for (int i = 0; i < 8; i++) {
        int dst = __shfl_sync(0xffffffffu, myidx, 8 + i);
        float4 hn;
        if (i < 7) {
            int sn = __shfl_sync(0xffffffffu, myidx, i + 1);
            hn = h4[(size_t)sn * 32 + lane];
        }
        uint2 pe = *(uint2*)&E[(rbase + i) * ESTR + lane * 4];
        float2 f0 = __half22float2(*(__half2*)&pe.x);
        float2 f1 = __half22float2(*(__half2*)&pe.y);
        float vx = fmaxf(hv.x + f0.x, 0.f);
        float vy = fmaxf(hv.y + f0.y, 0.f);
        float vz = fmaxf(hv.z + f1.x, 0.f);
        float vw = fmaxf(hv.w + f1.y, 0.f);
        float* ap = aggr + (size_t)dst * HID + lane * 4;
        asm volatile("red.global.add.v4.f32 [%0], {%1, %2, %3, %4};"
                     :: "l"(ap), "f"(vx), "f"(vy), "f"(vz), "f"(vw) : "memory");
        hv = hn;
    }
}

// ---------------- fused 2-layer MLP via tensor cores (2-phase W, 2 CTA/SM) ----------------
template <int KD, int MODE, bool RELU_OUT>
__global__ __launch_bounds__(256, 2) void mlp_mma(
    const float* __restrict__ in, int nrows,
    const float* __restrict__ w1, const float* __restrict__ b1,
    const float* __restrict__ w2, const float* __restrict__ b2,
    const float* __restrict__ xflag,
    float* __restrict__ out, float* __restrict__ out2)
{
    extern __shared__ __nv_bfloat16 smb[];
    __nv_bfloat16* Ah = smb;
    __nv_bfloat16* Al = Ah + 128 * ASTR;
    __nv_bfloat16* Wh = Al + 128 * ASTR;
    __nv_bfloat16* Wl = Wh + 128 * WSTR;

    const int tid = threadIdx.x;
    const int row0 = blockIdx.x * 128;

    for (int i = tid; i < 128 * (KD / 4); i += 256) {
        int r = i / (KD / 4), k4 = (i % (KD / 4)) * 4;
        float4 v = make_float4(0.f, 0.f, 0.f, 0.f);
        int gr = row0 + r;
        if (gr < nrows) v = *(const float4*)(in + (size_t)gr * KD + k4);
        __nv_bfloat16 h0, l0, h1, l1, h2, l2, h3, l3;
        bsplit(v.x, h0, l0); bsplit(v.y, h1, l1);
        bsplit(v.z, h2, l2); bsplit(v.w, h3, l3);
        *(__nv_bfloat162*)&Ah[r * ASTR + k4]     = __halves2bfloat162(h0, h1);
        *(__nv_bfloat162*)&Ah[r * ASTR + k4 + 2] = __halves2bfloat162(h2, h3);
        *(__nv_bfloat162*)&Al[r * ASTR + k4]     = __halves2bfloat162(l0, l1);
        *(__nv_bfloat162*)&Al[r * ASTR + k4 + 2] = __halves2bfloat162(l2, l3);
    }
    load_wt64(w1, 0, Wh, Wl, tid);
    __syncthreads();

    const int lane = tid & 31, wid = tid >> 5;
    const int r0 = (wid & 3) * 32, c0 = (wid >> 2) * 64;
    const int grp = lane >> 2, qp = lane & 3;

    float C[2][8][4];
    #pragma unroll
    for (int nt = 0; nt < 8; nt++) {
        float2 bv = *(const float2*)(b1 + c0 + nt * 8 + qp * 2);
        #pragma unroll
        for (int mt = 0; mt < 2; mt++) {
            C[mt][nt][0] = bv.x; C[mt][nt][1] = bv.y;
            C[mt][nt][2] = bv.x; C[mt][nt][3] = bv.y;
        }
    }
    warp_gemm<8>(Ah, Al, Wh, Wl, 4, ASTR, WSTR, 0, r0, c0, grp, qp, C);
    if (KD == 128) {
        __syncthreads();
        load_wt64(w1, 64, Wh, Wl, tid);
        __syncthreads();
        warp_gemm<8>(Ah, Al, Wh, Wl, 4, ASTR, WSTR, 64, r0, c0, grp, qp, C);
    }
    __syncthreads();

    #pragma unroll
    for (int mt = 0; mt < 2; mt++) {
        int row = r0 + mt * 16 + grp;
        #pragma unroll
        for (int nt = 0; nt < 8; nt++) {
            int col = c0 + nt * 8 + qp * 2;
            float v0 = fmaxf(C[mt][nt][0], 0.f), v1 = fmaxf(C[mt][nt][1], 0.f);
            float v2 = fmaxf(C[mt][nt][2], 0.f), v3 = fmaxf(C[mt][nt][3], 0.f);
            __nv_bfloat16 ha, la, hb, lb;
            bsplit(v0, ha, la); bsplit(v1, hb, lb);
            *(__nv_bfloat162*)&Ah[row * ASTR + col] = __halves2bfloat162(ha, hb);
            *(__nv_bfloat162*)&Al[row * ASTR + col] = __halves2bfloat162(la, lb);
            bsplit(v2, ha, la); bsplit(v3, hb, lb);
            *(__nv_bfloat162*)&Ah[(row + 8) * ASTR + col] = __halves2bfloat162(ha, hb);
            *(__nv_bfloat162*)&Al[(row + 8) * ASTR + col] = __halves2bfloat162(la, lb);
        }
    }
    __syncthreads();
    load_wt64(w2, 0, Wh, Wl, tid);
    __syncthreads();

    #pragma unroll
    for (int nt = 0; nt < 8; nt++) {
        float2 bv = *(const float2*)(b2 + c0 + nt * 8 + qp * 2);
        #pragma unroll
        for (int mt = 0; mt < 2; mt++) {
            C[mt][nt][0] = bv.x; C[mt][nt][1] = bv.y;
            C[mt][nt][2] = bv.x; C[mt][nt][3] = bv.y;
        }
    }
    warp_gemm<8>(Ah, Al, Wh, Wl, 4, ASTR, WSTR, 0, r0, c0, grp, qp, C);
    __syncthreads();
    load_wt64(w2, 64, Wh, Wl, tid);
    __syncthreads();
    warp_gemm<8>(Ah, Al, Wh, Wl, 4, ASTR, WSTR, 64, r0, c0, grp, qp, C);

    #pragma unroll
    for (int mt = 0; mt < 2; mt++) {
        #pragma unroll
        for (int rh = 0; rh < 2; rh++) {
            int gr = row0 + r0 + mt * 16 + grp + rh * 8;
            if (gr >= nrows) continue;
            if (MODE == 1) { if (xflag[(size_t)gr * IND + (IND - 1)] > 0.5f) continue; }
            if (MODE == 2) { if (!(xflag[(size_t)gr * IND + (IND - 1)] > 0.5f)) continue; }
            #pragma unroll
            for (int nt = 0; nt < 8; nt++) {
                int col = c0 + nt * 8 + qp * 2;
                float v0 = C[mt][nt][rh * 2 + 0], v1 = C[mt][nt][rh * 2 + 1];
                if (RELU_OUT) { v0 = fmaxf(v0, 0.f); v1 = fmaxf(v1, 0.f); }
                float2 o = make_float2(v0, v1);
                *(float2*)(out + (size_t)gr * HID + col) = o;
                if (out2) *(float2*)(out2 + (size_t)gr * HID + col) = o;
            }
        }
    }
}

// ---------------- GraphNorm: fused sum+sumsq pass, then normalize (+pool) ----------------
__global__ __launch_bounds__(512) void gnorm_kernel(
    const float* __restrict__ in, float* __restrict__ out,
    float* __restrict__ out2,
    const float* __restrict__ gw, const float* __restrict__ gb,
    const float* __restrict__ gms, int do_pool)
{
    __shared__ float red[4 * HID];
    __shared__ float red2[4 * HID];
    __shared__ float statm[HID];
    __shared__ float statr[HID];
    int g = blockIdx.x;
    int tid = threadIdx.x;
    int c = tid & (HID - 1);
    int sub = tid >> 7;
    int s = d_off[g], e = d_off[g + 1];
    float cnt = fmaxf((float)(e - s), 1.f);

    float sum = 0.f, ssq = 0.f;
    for (int n = s + sub; n < e; n += 4) {
        float v = in[(size_t)n * HID + c];
        sum += v;
        ssq += v * v;
    }
    red[sub * HID + c] = sum;
    red2[sub * HID + c] = ssq;
    __syncthreads();
    if (sub == 0) {
        float tot  = red[c] + red[HID + c] + red[2 * HID + c] + red[3 * HID + c];
        float tsq  = red2[c] + red2[HID + c] + red2[2 * HID + c] + red2[3 * HID + c];
        float meanx = tot / cnt;
        float m = meanx * gms[c];                          // subtracted mean
        float var = tsq / cnt - 2.f * m * meanx + m * m;   // E[(x-m)^2]
        statm[c] = m;
        statr[c] = rsqrtf(var + EPSV);
    }
    __syncthreads();
    float m = statm[c];
    float w = gw[c] * statr[c];
    float b = gb[c];

    float pool = 0.f;
    for (int n = s + sub; n < e; n += 4) {
        float v = fmaxf((in[(size_t)n * HID + c] - m) * w + b, 0.f);
        out[(size_t)n * HID + c] = v;
        if (out2) out2[(size_t)n * HID + c] = v;
        pool += v;
    }
    if (do_pool) {
        __syncthreads();
        red[sub * HID + c] = pool;
        __syncthreads();
        if (sub == 0)
            d_g[g * HID + c] = red[c] + red[HID + c] + red[2 * HID + c] + red[3 * HID + c];
    }
}

// ---------------- output head ----------------
__global__ __launch_bounds__(128) void head_kernel(
    const float* __restrict__ fw1, const float* __restrict__ fb1,
    const float* __restrict__ fw2, const float* __restrict__ fb2,
    float* __restrict__ outp)
{
    int i = blockIdx.x;
    int c = threadIdx.x;
    __shared__ float gs[HID];
    __shared__ float red[HID];
    gs[c] = d_g[i * HID + c];
    __syncthreads();
    float acc = fb1[c];
    #pragma unroll 4
    for (int k = 0; k < HID; k++) acc += gs[k] * fw1[k * HID + c];
    red[c] = fmaxf(acc, 0.f) * fw2[c];
    __syncthreads();
    for (int s = 64; s > 0; s >>= 1) {
        if (c < s) red[c] += red[c + s];
        __syncthreads();
    }
    if (c == 0) outp[i] = red[0] + fb2[0];
}

// ---------------- launch ----------------
extern "C" void kernel_launch(void* const* d_in, const int* in_sizes, int n_in,
                              void* d_out, int out_size)
{
    const float* x     = (const float*)d_in[0];
    const int*   ei    = (const int*)d_in[1];
    const float* ea    = (const float*)d_in[2];
    const int*   batch = (const int*)d_in[3];
    const float* lig_w1 = (const float*)d_in[4];
    const float* lig_b1 = (const float*)d_in[5];
    const float* lig_w2 = (const float*)d_in[6];
    const float* lig_b2 = (const float*)d_in[7];
    const float* prot_w1 = (const float*)d_in[8];
    const float* prot_b1 = (const float*)d_in[9];
    const float* prot_w2 = (const float*)d_in[10];
    const float* prot_b2 = (const float*)d_in[11];
    const float* edge_w = (const float*)d_in[12];
    const float* edge_b = (const float*)d_in[13];
    const float* nn_w1 = (const float*)d_in[14];
    const float* nn_b1 = (const float*)d_in[15];
    const float* nn_w2 = (const float*)d_in[16];
    const float* nn_b2 = (const float*)d_in[17];
    const float* gn_w = (const float*)d_in[18];
    const float* gn_b = (const float*)d_in[19];
    const float* gn_ms = (const float*)d_in[20];
    const float* fc_w1 = (const float*)d_in[21];
    const float* fc_b1 = (const float*)d_in[22];
    const float* fc_w2 = (const float*)d_in[23];
    const float* fc_b2 = (const float*)d_in[24];
    float* outp = (float*)d_out;

    float* hptr = nullptr; float* tptr = nullptr;
    cudaGetSymbolAddress((void**)&hptr, d_h);
    cudaGetSymbolAddress((void**)&tptr, d_t);

    const int SMEM_MLP = (2 * 128 * ASTR + 2 * 128 * WSTR) * (int)sizeof(__nv_bfloat16); // 101376 B
    const int SMEM_MSG = 4 * 128 * EASTR * (int)sizeof(__nv_bfloat16)
                       + 128 * ESTR * (int)sizeof(__half);                               // 54272 B
    cudaFuncSetAttribute(mlp_mma<IND, 1, true>,  cudaFuncAttributeMaxDynamicSharedMemorySize, SMEM_MLP);
    cudaFuncSetAttribute(mlp_mma<IND, 2, true>,  cudaFuncAttributeMaxDynamicSharedMemorySize, SMEM_MLP);
    cudaFuncSetAttribute(mlp_mma<HID, 0, false>, cudaFuncAttributeMaxDynamicSharedMemorySize, SMEM_MLP);
    cudaFuncSetAttribute(msg_mma, cudaFuncAttributeMaxDynamicSharedMemorySize, SMEM_MSG);

    offsets_kernel<<<1, 256>>>(batch);

    dim3 gB((NN + 127) / 128);  // 391 blocks
    // encoders write h AND seed aggr buffer (t) with h  — msg_mma is launch #4 (ncu window)
    mlp_mma<IND, 1, true><<<gB, 256, SMEM_MLP>>>(x, NN, lig_w1, lig_b1, lig_w2, lig_b2, x, hptr, tptr);
    mlp_mma<IND, 2, true><<<gB, 256, SMEM_MLP>>>(x, NN, prot_w1, prot_b1, prot_w2, prot_b2, x, hptr, tptr);

    for (int l = 0; l < 3; l++) {
        msg_mma<<<NE / 128, 512, SMEM_MSG>>>(ei, ea,
                                             edge_w + (size_t)l * ED * HID,
                                             edge_b + (size_t)l * HID,
                                             hptr, tptr);
        mlp_mma<HID, 0, false><<<gB, 256, SMEM_MLP>>>(
            tptr, NN,
            nn_w1 + (size_t)l * HID * HID, nn_b1 + (size_t)l * HID,
            nn_w2 + (size_t)l * HID * HID, nn_b2 + (size_t)l * HID,
            nullptr, tptr, nullptr);
        gnorm_kernel<<<GG, 512>>>(tptr, hptr, (l < 2) ? tptr : nullptr,
                                  gn_w + (size_t)l * HID, gn_b + (size_t)l * HID,
                                  gn_ms + (size_t)l * HID, (l == 2) ? 1 : 0);
    }

    head_kernel<<<GG, 128>>>(fc_w1, fc_b1, fc_w2, fc_b2, outp);
}